// round 11
// baseline (speedup 1.0000x reference)
#include <cuda_runtime.h>
#include <cuda_bf16.h>
#include <cstdint>

// -------- scratch (device globals; no allocation allowed) --------
#define NMAX 100000

__device__ __align__(16) float g_agg1[(size_t)NMAX * 32]; // sum of neighbor x rows
__device__ __align__(16) float g_agg2[(size_t)NMAX * 16]; // sum of neighbor z2 rows
__device__ __align__(16) float g_z2[(size_t)NMAX * 16];   // h @ W2l
__device__ __align__(16) float g_r2[(size_t)NMAX * 16];   // h @ W2r + b2
__device__ float g_deg[NMAX];
__device__ int g_is64;

// -------- zero agg1/agg2/deg + sniff dtype (block 0) --------
__global__ void zero_sniff_kernel(float4* __restrict__ agg1, size_t n1,
                                  float4* __restrict__ agg2, size_t n2,
                                  float* __restrict__ deg, int nd,
                                  const unsigned int* __restrict__ w,
                                  int nsamples) {
    size_t i = (size_t)blockIdx.x * blockDim.x + threadIdx.x;
    size_t stride = (size_t)gridDim.x * blockDim.x;
    float4 z = make_float4(0.f, 0.f, 0.f, 0.f);
    for (size_t k = i; k < n1; k += stride) agg1[k] = z;
    for (size_t k = i; k < n2; k += stride) agg2[k] = z;
    for (size_t k = i; k < (size_t)nd; k += stride) deg[k] = 0.0f;
    if (blockIdx.x == 0) {
        int nz = 0;
        for (int k = threadIdx.x; k < nsamples; k += blockDim.x)
            nz |= (w[2 * k + 1] != 0u) ? 1 : 0;
        nz = __syncthreads_or(nz);
        if (threadIdx.x == 0) g_is64 = nz ? 0 : 1;
    }
}

// -------- scatter layer 1: agg1[dst] += x[src] (128B rows), deg[dst] += 1 --------
// Warp-cooperative: 8 edges/warp. Lanes 0-7 load src ids, lanes 8-15 load dst
// ids (coalesced); shfl-distributed. 4 threads/edge, each handles 2 float4
// chunks (c and c+4). Vector RED.128 per chunk.
__global__ void scatter1_kernel(const float* __restrict__ x,
                                const void* __restrict__ ei,
                                float* __restrict__ agg1,
                                float* __restrict__ deg,
                                int E, int N) {
    int is64 = g_is64;
    int lane = threadIdx.x & 31;
    int warp = (blockIdx.x * blockDim.x + threadIdx.x) >> 5;
    int base = warp * 8;
    if (base >= E) return;                     // warp-uniform exit

    // cooperative index load: lanes 0-7 -> src[base+l], lanes 8-15 -> dst[base+l-8]
    int idx = 0;
    int which = (lane >> 3) & 1;               // 0 = src row, 1 = dst row
    int off = lane & 7;
    int epos = base + off;
    if (lane < 16 && epos < E) {
        if (is64) idx = (int)((const long long*)ei)[(size_t)which * E + epos];
        else      idx = ((const int*)ei)[(size_t)which * E + epos];
    }

    int eidx = lane >> 2;                      // 0..7: edge within warp
    int c = lane & 3;                          // chunk id (handles c and c+4)
    int s = __shfl_sync(0xffffffffu, idx, eidx);
    int d = __shfl_sync(0xffffffffu, idx, 8 + eidx);
    if (base + eidx >= E) return;              // after shfl: safe

    s = min(max(s, 0), N - 1);
    d = min(max(d, 0), N - 1);
    const float4* xs = (const float4*)(x + (size_t)s * 32);
    float4 v0 = xs[c];
    float4 v1 = xs[c + 4];
    float4* ad = (float4*)(agg1 + (size_t)d * 32);
    atomicAdd(ad + c, v0);
    atomicAdd(ad + c + 4, v1);
    if (c == 0) atomicAdd(&deg[d], 1.0f);
}

// -------- fused dense: mean = agg1/deg; h = relu(mean@W1l + x@W1r + b1);
//          z2 = h@W2l; r2 = h@W2r + b2 --------
__global__ void dense_kernel(const float* __restrict__ x,
                             const float* __restrict__ agg1,
                             const float* __restrict__ deg,
                             const float* __restrict__ W1l,
                             const float* __restrict__ W1r,
                             const float* __restrict__ b1,
                             const float* __restrict__ W2l,
                             const float* __restrict__ W2r,
                             const float* __restrict__ b2,
                             float* __restrict__ z2,
                             float* __restrict__ r2, int N) {
    int lane = threadIdx.x & 31;
    int warp = (blockIdx.x * blockDim.x + threadIdx.x) >> 5;
    int nwarps = (gridDim.x * blockDim.x) >> 5;

    float wl1[32], wr1[32], w2[32];
#pragma unroll
    for (int k = 0; k < 32; k++) {
        wl1[k] = W1l[k * 32 + lane];
        wr1[k] = W1r[k * 32 + lane];
    }
    int j = lane & 15;
    bool left = lane < 16;
#pragma unroll
    for (int k = 0; k < 32; k++)
        w2[k] = left ? W2l[k * 16 + j] : W2r[k * 16 + j];
    float b1j = b1[lane];
    float b2j = left ? 0.0f : b2[j];

    for (int n = warp; n < N; n += nwarps) {
        float inv = 1.0f / fmaxf(deg[n], 1.0f);
        float mv = agg1[(size_t)n * 32 + lane] * inv;
        float xv = x[(size_t)n * 32 + lane];

        float r = b1j;
#pragma unroll
        for (int k = 0; k < 32; k++) {
            float mk = __shfl_sync(0xffffffffu, mv, k);
            float xk = __shfl_sync(0xffffffffu, xv, k);
            r = fmaf(mk, wl1[k], fmaf(xk, wr1[k], r));
        }
        float h = fmaxf(r, 0.0f);

        float acc = b2j;
#pragma unroll
        for (int k = 0; k < 32; k++) {
            float hk = __shfl_sync(0xffffffffu, h, k);
            acc = fmaf(hk, w2[k], acc);
        }
        if (left) z2[(size_t)n * 16 + j] = acc;
        else      r2[(size_t)n * 16 + j] = acc;
    }
}

// -------- scatter layer 2: agg2[dst] += z2[src] (64B rows) --------
// Warp-cooperative: 16 edges/warp. Lanes 0-15 load src ids, 16-31 load dst
// ids; shfl-distributed. 2 threads/edge, each handles 2 float4 chunks.
__global__ void scatter2_kernel(const float* __restrict__ z2,
                                const void* __restrict__ ei,
                                float* __restrict__ agg2,
                                int E, int N) {
    int is64 = g_is64;
    int lane = threadIdx.x & 31;
    int warp = (blockIdx.x * blockDim.x + threadIdx.x) >> 5;
    int base = warp * 16;
    if (base >= E) return;                     // warp-uniform exit

    int which = lane >> 4;                     // 0 = src row, 1 = dst row
    int off = lane & 15;
    int epos = base + off;
    int idx = 0;
    if (epos < E) {
        if (is64) idx = (int)((const long long*)ei)[(size_t)which * E + epos];
        else      idx = ((const int*)ei)[(size_t)which * E + epos];
    }

    int eidx = lane >> 1;                      // 0..15: edge within warp
    int c = lane & 1;                          // chunk id (handles c and c+2)
    int s = __shfl_sync(0xffffffffu, idx, eidx);
    int d = __shfl_sync(0xffffffffu, idx, 16 + eidx);
    if (base + eidx >= E) return;              // after shfl: safe

    s = min(max(s, 0), N - 1);
    d = min(max(d, 0), N - 1);
    const float4* zs = (const float4*)(z2 + (size_t)s * 16);
    float4 v0 = zs[c];
    float4 v1 = zs[c + 2];
    float4* ad = (float4*)(agg2 + (size_t)d * 16);
    atomicAdd(ad + c, v0);
    atomicAdd(ad + c + 2, v1);
}

// -------- epilogue: out[n] = agg2[n]/max(deg,1) + r2[n]  (N x 16) --------
__global__ void epilogue_kernel(const float* __restrict__ agg2,
                                const float* __restrict__ r2,
                                const float* __restrict__ deg,
                                float* __restrict__ out, int N) {
    int i = blockIdx.x * blockDim.x + threadIdx.x;   // one float4 per thread
    int total = N * 4;
    if (i >= total) return;
    int n = i >> 2;
    float inv = 1.0f / fmaxf(deg[n], 1.0f);
    float4 a = ((const float4*)agg2)[i];
    float4 rr = ((const float4*)r2)[i];
    float4 o = make_float4(a.x * inv + rr.x, a.y * inv + rr.y,
                           a.z * inv + rr.z, a.w * inv + rr.w);
    ((float4*)out)[i] = o;
}

extern "C" void kernel_launch(void* const* d_in, const int* in_sizes, int n_in,
                              void* d_out, int out_size) {
    const float* x   = (const float*)d_in[0];
    const void*  ei  = d_in[1];
    const float* W1l = (const float*)d_in[2];
    const float* W1r = (const float*)d_in[3];
    const float* b1  = (const float*)d_in[4];
    const float* W2l = (const float*)d_in[5];
    const float* W2r = (const float*)d_in[6];
    const float* b2  = (const float*)d_in[7];
    float* out = (float*)d_out;

    int N = in_sizes[0] / 32;   // 100000
    int E = in_sizes[1] / 2;    // 1600000

    float *agg1, *agg2, *z2, *r2, *deg;
    cudaGetSymbolAddress((void**)&agg1, g_agg1);
    cudaGetSymbolAddress((void**)&agg2, g_agg2);
    cudaGetSymbolAddress((void**)&z2, g_z2);
    cudaGetSymbolAddress((void**)&r2, g_r2);
    cudaGetSymbolAddress((void**)&deg, g_deg);

    size_t n1 = (size_t)N * 32 / 4;   // agg1 float4 count
    size_t n2 = (size_t)N * 16 / 4;   // agg2 float4 count

    // 1: zero scratch + sniff dtype
    zero_sniff_kernel<<<2048, 256>>>((float4*)agg1, n1, (float4*)agg2, n2,
                                     deg, N, (const unsigned int*)ei, 4096);
    // 2: scatter layer 1 (8 edges/warp, warp-coop indices)
    {
        int warps = (E + 7) / 8;
        int blocks = (warps + 7) / 8;          // 8 warps per 256-thread block
        scatter1_kernel<<<blocks, 256>>>(x, ei, agg1, deg, E, N);
    }
    // 3: fused dense (layer-1 linear+relu, layer-2 transform)
    dense_kernel<<<2048, 256>>>(x, agg1, deg, W1l, W1r, b1, W2l, W2r, b2,
                                z2, r2, N);
    // 4: scatter layer 2 (16 edges/warp, warp-coop indices)
    {
        int warps = (E + 15) / 16;
        int blocks = (warps + 7) / 8;
        scatter2_kernel<<<blocks, 256>>>(z2, ei, agg2, E, N);
    }
    // 5: epilogue
    epilogue_kernel<<<(N * 4 + 255) / 256, 256>>>(agg2, r2, deg, out, N);
}

// round 12
// speedup vs baseline: 1.0449x; 1.0449x over previous
#include <cuda_runtime.h>
#include <cuda_bf16.h>
#include <cstdint>

// -------- scratch (device globals; no allocation allowed) --------
#define NMAX 100000
#define EMAX 1600000
#define NB_MAX 128            // ceil(NMAX/1024) = 98 <= 128

__device__ __align__(16) float g_mean[(size_t)NMAX * 32]; // mean of neighbor x rows
__device__ __align__(16) float g_z2[(size_t)NMAX * 16];   // h @ W2l
__device__ __align__(16) float g_r2[(size_t)NMAX * 16];   // h @ W2r + b2
__device__ int g_rowptr[NMAX + 1];
__device__ int g_cnt[NMAX];
__device__ int g_cursor[NMAX];
__device__ int g_csr_src[EMAX];
__device__ int g_bsum[NB_MAX];
__device__ int g_is64;

// -------- zero cnt + sniff dtype (block 0) --------
__global__ void zero_sniff_kernel(int* __restrict__ cnt, int n,
                                  const unsigned int* __restrict__ w,
                                  int nsamples) {
    int i = blockIdx.x * blockDim.x + threadIdx.x;
    if (i < n) cnt[i] = 0;
    if (blockIdx.x == 0) {
        int nz = 0;
        for (int k = threadIdx.x; k < nsamples; k += blockDim.x)
            nz |= (w[2 * k + 1] != 0u) ? 1 : 0;
        nz = __syncthreads_or(nz);
        if (threadIdx.x == 0) g_is64 = nz ? 0 : 1;
    }
}

// -------- count in-degree: 4 edges per thread (MLP 2-4 on index loads) --------
__global__ void count_kernel(const void* __restrict__ ei,
                             int* __restrict__ cnt, int E, int N) {
    int is64 = g_is64;
    int stride = gridDim.x * blockDim.x;
    int Q = E >> 2;   // E divisible by 4
    if (is64) {
        const longlong2* p = (const longlong2*)((const long long*)ei + E);
        for (int q = blockIdx.x * blockDim.x + threadIdx.x; q < Q; q += stride) {
            longlong2 a = p[2 * q];
            longlong2 b = p[2 * q + 1];
            int d0 = (int)a.x, d1 = (int)a.y, d2 = (int)b.x, d3 = (int)b.y;
            if (d0 >= 0 && d0 < N) atomicAdd(&cnt[d0], 1);
            if (d1 >= 0 && d1 < N) atomicAdd(&cnt[d1], 1);
            if (d2 >= 0 && d2 < N) atomicAdd(&cnt[d2], 1);
            if (d3 >= 0 && d3 < N) atomicAdd(&cnt[d3], 1);
        }
    } else {
        const int4* p = (const int4*)((const int*)ei + E);
        for (int q = blockIdx.x * blockDim.x + threadIdx.x; q < Q; q += stride) {
            int4 v = p[q];
            if (v.x >= 0 && v.x < N) atomicAdd(&cnt[v.x], 1);
            if (v.y >= 0 && v.y < N) atomicAdd(&cnt[v.y], 1);
            if (v.z >= 0 && v.z < N) atomicAdd(&cnt[v.z], 1);
            if (v.w >= 0 && v.w < N) atomicAdd(&cnt[v.w], 1);
        }
    }
}

// -------- scan stage 1: per-1024-block exclusive scan + block totals --------
__global__ void scan1_kernel(const int* __restrict__ cnt,
                             int* __restrict__ rowptr,
                             int* __restrict__ bsum, int N) {
    __shared__ int sh[1024];
    int gid = blockIdx.x * 1024 + threadIdx.x;
    int v = (gid < N) ? cnt[gid] : 0;
    sh[threadIdx.x] = v;
    __syncthreads();
    for (int off = 1; off < 1024; off <<= 1) {
        int t = (threadIdx.x >= off) ? sh[threadIdx.x - off] : 0;
        __syncthreads();
        sh[threadIdx.x] += t;
        __syncthreads();
    }
    if (gid < N) rowptr[gid] = sh[threadIdx.x] - v;   // exclusive within block
    if (threadIdx.x == 1023) bsum[blockIdx.x] = sh[1023];
}

// -------- scan stage 2+3 fused: finalize rowptr, zero cursors --------
__global__ void scan23_kernel(int* __restrict__ rowptr,
                              const int* __restrict__ bsum,
                              int* __restrict__ cursor, int N, int E, int nb) {
    __shared__ int sh[NB_MAX];
    if (threadIdx.x < NB_MAX)
        sh[threadIdx.x] = (threadIdx.x < nb) ? bsum[threadIdx.x] : 0;
    __syncthreads();
    for (int off = 1; off < NB_MAX; off <<= 1) {
        int t = (threadIdx.x < NB_MAX && threadIdx.x >= off) ? sh[threadIdx.x - off] : 0;
        __syncthreads();
        if (threadIdx.x < NB_MAX) sh[threadIdx.x] += t;   // inclusive
        __syncthreads();
    }
    int gid = blockIdx.x * blockDim.x + threadIdx.x;
    if (gid < N) {
        int w = gid >> 10;
        rowptr[gid] += (w > 0) ? sh[w - 1] : 0;
        cursor[gid] = 0;
    }
    if (gid == 0) rowptr[N] = E;
}

// -------- fill CSR: 4 edges per thread --------
__global__ void fill_kernel(const void* __restrict__ ei,
                            const int* __restrict__ rowptr,
                            int* __restrict__ cursor,
                            int* __restrict__ csr_src, int E, int N) {
    int is64 = g_is64;
    int stride = gridDim.x * blockDim.x;
    int Q = E >> 2;
    for (int q = blockIdx.x * blockDim.x + threadIdx.x; q < Q; q += stride) {
        int s0, s1, s2, s3, d0, d1, d2, d3;
        if (is64) {
            const longlong2* ps = (const longlong2*)ei;
            const longlong2* pd = (const longlong2*)((const long long*)ei + E);
            longlong2 sa = ps[2 * q], sb = ps[2 * q + 1];
            longlong2 da = pd[2 * q], db = pd[2 * q + 1];
            s0 = (int)sa.x; s1 = (int)sa.y; s2 = (int)sb.x; s3 = (int)sb.y;
            d0 = (int)da.x; d1 = (int)da.y; d2 = (int)db.x; d3 = (int)db.y;
        } else {
            const int4* ps = (const int4*)ei;
            const int4* pd = (const int4*)((const int*)ei + E);
            int4 sv = ps[q], dv = pd[q];
            s0 = sv.x; s1 = sv.y; s2 = sv.z; s3 = sv.w;
            d0 = dv.x; d1 = dv.y; d2 = dv.z; d3 = dv.w;
        }
        if (d0 >= 0 && d0 < N) { int p = atomicAdd(&cursor[d0], 1); csr_src[rowptr[d0] + p] = s0; }
        if (d1 >= 0 && d1 < N) { int p = atomicAdd(&cursor[d1], 1); csr_src[rowptr[d1] + p] = s1; }
        if (d2 >= 0 && d2 < N) { int p = atomicAdd(&cursor[d2], 1); csr_src[rowptr[d2] + p] = s2; }
        if (d3 >= 0 && d3 < N) { int p = atomicAdd(&cursor[d3], 1); csr_src[rowptr[d3] + p] = s3; }
    }
}

// -------- gather 1: mean[n] = (1/deg) * sum_{s in N(n)} x[s]   (rows 128B) --------
// Warp per node. 4 groups x 8 lanes; stride 16 -> 16 rows in flight per warp.
__global__ void gather1_kernel(const float* __restrict__ x,
                               const int* __restrict__ rowptr,
                               const int* __restrict__ csr_src,
                               float* __restrict__ mean, int N) {
    int lane = threadIdx.x & 31;
    int g = lane >> 3;          // 0..3
    int c = lane & 7;           // 0..7
    int n = blockIdx.x * (blockDim.x >> 5) + (threadIdx.x >> 5);
    if (n >= N) return;

    int s0 = rowptr[n];
    int s1 = rowptr[n + 1];
    int deg = s1 - s0;

    float4 a0 = make_float4(0.f, 0.f, 0.f, 0.f);
    float4 a1 = make_float4(0.f, 0.f, 0.f, 0.f);
    float4 a2 = make_float4(0.f, 0.f, 0.f, 0.f);
    float4 a3 = make_float4(0.f, 0.f, 0.f, 0.f);
    for (int e = s0; e < s1; e += 16) {         // warp-uniform bound
        int i0 = e + g, i1 = e + 4 + g, i2 = e + 8 + g, i3 = e + 12 + g;
        bool v0 = i0 < s1, v1 = i1 < s1, v2 = i2 < s1, v3 = i3 < s1;
        int sid0 = v0 ? csr_src[i0] : 0;
        int sid1 = v1 ? csr_src[i1] : 0;
        int sid2 = v2 ? csr_src[i2] : 0;
        int sid3 = v3 ? csr_src[i3] : 0;
        float4 r0 = ((const float4*)(x + (size_t)sid0 * 32))[c];
        float4 r1 = ((const float4*)(x + (size_t)sid1 * 32))[c];
        float4 r2 = ((const float4*)(x + (size_t)sid2 * 32))[c];
        float4 r3 = ((const float4*)(x + (size_t)sid3 * 32))[c];
        if (v0) { a0.x += r0.x; a0.y += r0.y; a0.z += r0.z; a0.w += r0.w; }
        if (v1) { a1.x += r1.x; a1.y += r1.y; a1.z += r1.z; a1.w += r1.w; }
        if (v2) { a2.x += r2.x; a2.y += r2.y; a2.z += r2.z; a2.w += r2.w; }
        if (v3) { a3.x += r3.x; a3.y += r3.y; a3.z += r3.z; a3.w += r3.w; }
    }
    a0.x += a1.x; a0.y += a1.y; a0.z += a1.z; a0.w += a1.w;
    a2.x += a3.x; a2.y += a3.y; a2.z += a3.z; a2.w += a3.w;
    a0.x += a2.x; a0.y += a2.y; a0.z += a2.z; a0.w += a2.w;
#pragma unroll
    for (int s = 8; s <= 16; s <<= 1) {
        a0.x += __shfl_xor_sync(0xffffffffu, a0.x, s);
        a0.y += __shfl_xor_sync(0xffffffffu, a0.y, s);
        a0.z += __shfl_xor_sync(0xffffffffu, a0.z, s);
        a0.w += __shfl_xor_sync(0xffffffffu, a0.w, s);
    }
    if (g == 0) {
        float inv = 1.0f / (float)max(deg, 1);
        float4 m = make_float4(a0.x * inv, a0.y * inv, a0.z * inv, a0.w * inv);
        ((float4*)(mean + (size_t)n * 32))[c] = m;
    }
}

// -------- fused dense: h = relu(mean@W1l + x@W1r + b1); z2 = h@W2l; r2 = h@W2r + b2 --------
__global__ void dense_kernel(const float* __restrict__ x,
                             const float* __restrict__ mean,
                             const float* __restrict__ W1l,
                             const float* __restrict__ W1r,
                             const float* __restrict__ b1,
                             const float* __restrict__ W2l,
                             const float* __restrict__ W2r,
                             const float* __restrict__ b2,
                             float* __restrict__ z2,
                             float* __restrict__ r2, int N) {
    int lane = threadIdx.x & 31;
    int warp = (blockIdx.x * blockDim.x + threadIdx.x) >> 5;
    int nwarps = (gridDim.x * blockDim.x) >> 5;

    float wl1[32], wr1[32], w2[32];
#pragma unroll
    for (int k = 0; k < 32; k++) {
        wl1[k] = W1l[k * 32 + lane];
        wr1[k] = W1r[k * 32 + lane];
    }
    int j = lane & 15;
    bool left = lane < 16;
#pragma unroll
    for (int k = 0; k < 32; k++)
        w2[k] = left ? W2l[k * 16 + j] : W2r[k * 16 + j];
    float b1j = b1[lane];
    float b2j = left ? 0.0f : b2[j];

    for (int n = warp; n < N; n += nwarps) {
        float mv = mean[(size_t)n * 32 + lane];
        float xv = x[(size_t)n * 32 + lane];

        float r = b1j;
#pragma unroll
        for (int k = 0; k < 32; k++) {
            float mk = __shfl_sync(0xffffffffu, mv, k);
            float xk = __shfl_sync(0xffffffffu, xv, k);
            r = fmaf(mk, wl1[k], fmaf(xk, wr1[k], r));
        }
        float h = fmaxf(r, 0.0f);

        float acc = b2j;
#pragma unroll
        for (int k = 0; k < 32; k++) {
            float hk = __shfl_sync(0xffffffffu, h, k);
            acc = fmaf(hk, w2[k], acc);
        }
        if (left) z2[(size_t)n * 16 + j] = acc;
        else      r2[(size_t)n * 16 + j] = acc;
    }
}

// -------- gather 2: out[n] = (1/deg) * sum_{s} z2[s] + r2[n]   (rows 64B) --------
// Warp per node. 8 groups x 4 lanes; stride 16 -> 16 rows in flight per warp.
__global__ void gather2_kernel(const float* __restrict__ z2,
                               const float* __restrict__ r2,
                               const int* __restrict__ rowptr,
                               const int* __restrict__ csr_src,
                               float* __restrict__ out, int N) {
    int lane = threadIdx.x & 31;
    int g = lane >> 2;          // 0..7
    int c = lane & 3;           // 0..3
    int n = blockIdx.x * (blockDim.x >> 5) + (threadIdx.x >> 5);
    if (n >= N) return;

    int s0 = rowptr[n];
    int s1 = rowptr[n + 1];
    int deg = s1 - s0;

    float4 a0 = make_float4(0.f, 0.f, 0.f, 0.f);
    float4 a1 = make_float4(0.f, 0.f, 0.f, 0.f);
    for (int e = s0; e < s1; e += 16) {        // warp-uniform bound
        int i0 = e + g;
        int i1 = e + 8 + g;
        bool v0 = i0 < s1;
        bool v1 = i1 < s1;
        int sid0 = v0 ? csr_src[i0] : 0;
        int sid1 = v1 ? csr_src[i1] : 0;
        float4 r0 = ((const float4*)(z2 + (size_t)sid0 * 16))[c];
        float4 r1 = ((const float4*)(z2 + (size_t)sid1 * 16))[c];
        if (v0) { a0.x += r0.x; a0.y += r0.y; a0.z += r0.z; a0.w += r0.w; }
        if (v1) { a1.x += r1.x; a1.y += r1.y; a1.z += r1.z; a1.w += r1.w; }
    }
    a0.x += a1.x; a0.y += a1.y; a0.z += a1.z; a0.w += a1.w;
#pragma unroll
    for (int s = 4; s <= 16; s <<= 1) {
        a0.x += __shfl_xor_sync(0xffffffffu, a0.x, s);
        a0.y += __shfl_xor_sync(0xffffffffu, a0.y, s);
        a0.z += __shfl_xor_sync(0xffffffffu, a0.z, s);
        a0.w += __shfl_xor_sync(0xffffffffu, a0.w, s);
    }
    if (g == 0) {
        float inv = 1.0f / (float)max(deg, 1);
        float4 rr = ((const float4*)(r2 + (size_t)n * 16))[c];
        float4 o = make_float4(a0.x * inv + rr.x, a0.y * inv + rr.y,
                               a0.z * inv + rr.z, a0.w * inv + rr.w);
        ((float4*)(out + (size_t)n * 16))[c] = o;
    }
}

extern "C" void kernel_launch(void* const* d_in, const int* in_sizes, int n_in,
                              void* d_out, int out_size) {
    const float* x   = (const float*)d_in[0];
    const void*  ei  = d_in[1];
    const float* W1l = (const float*)d_in[2];
    const float* W1r = (const float*)d_in[3];
    const float* b1  = (const float*)d_in[4];
    const float* W2l = (const float*)d_in[5];
    const float* W2r = (const float*)d_in[6];
    const float* b2  = (const float*)d_in[7];
    float* out = (float*)d_out;

    int N = in_sizes[0] / 32;   // 100000
    int E = in_sizes[1] / 2;    // 1600000

    float *mean, *z2, *r2;
    int *rowptr, *cnt, *cursor, *csr_src, *bsum;
    cudaGetSymbolAddress((void**)&mean, g_mean);
    cudaGetSymbolAddress((void**)&z2, g_z2);
    cudaGetSymbolAddress((void**)&r2, g_r2);
    cudaGetSymbolAddress((void**)&rowptr, g_rowptr);
    cudaGetSymbolAddress((void**)&cnt, g_cnt);
    cudaGetSymbolAddress((void**)&cursor, g_cursor);
    cudaGetSymbolAddress((void**)&csr_src, g_csr_src);
    cudaGetSymbolAddress((void**)&bsum, g_bsum);

    int nb = (N + 1023) / 1024;           // 98
    int gblocks = (N + 7) / 8;            // 8 warps per 256-thread block

    // ---- CSR build ----
    zero_sniff_kernel<<<(N + 255) / 256, 256>>>(cnt, N, (const unsigned int*)ei, 4096);
    count_kernel<<<1024, 256>>>(ei, cnt, E, N);
    scan1_kernel<<<nb, 1024>>>(cnt, rowptr, bsum, N);
    scan23_kernel<<<(N + 255) / 256, 256>>>(rowptr, bsum, cursor, N, E, nb);
    fill_kernel<<<1024, 256>>>(ei, rowptr, cursor, csr_src, E, N);

    // ---- layer 1 gather ----
    gather1_kernel<<<gblocks, 256>>>(x, rowptr, csr_src, mean, N);
    // ---- fused dense ----
    dense_kernel<<<2048, 256>>>(x, mean, W1l, W1r, b1, W2l, W2r, b2, z2, r2, N);
    // ---- layer 2 gather + epilogue ----
    gather2_kernel<<<gblocks, 256>>>(z2, r2, rowptr, csr_src, out, N);
}

// round 14
// speedup vs baseline: 1.0700x; 1.0241x over previous
#include <cuda_runtime.h>
#include <cuda_fp16.h>
#include <cstdint>

// -------- scratch (device globals; no allocation allowed) --------
#define NMAX 100000
#define EMAX 1600000
#define NB_MAX 128            // ceil(NMAX/1024) = 98 <= 128

__device__ __align__(16) __half g_xh[(size_t)NMAX * 32];  // x in fp16
__device__ __align__(16) float g_mean[(size_t)NMAX * 32]; // mean of neighbor x rows (fp32)
__device__ __align__(16) __half g_z2h[(size_t)NMAX * 16]; // h @ W2l in fp16
__device__ __align__(16) float g_r2[(size_t)NMAX * 16];   // h @ W2r + b2 (fp32)
__device__ int g_rowptr[NMAX + 1];
__device__ int g_cnt[NMAX];
__device__ int g_cursor[NMAX];
__device__ int g_csr_src[EMAX];
__device__ int g_bsum[NB_MAX];
__device__ int g_is64;

// bit-cast helpers (no intrinsics needed)
__device__ __forceinline__ unsigned h2_to_u32(__half2 h) {
    return *reinterpret_cast<unsigned*>(&h);
}
__device__ __forceinline__ __half2 u32_to_h2(unsigned u) {
    return *reinterpret_cast<__half2*>(&u);
}

// -------- zero cnt + convert x->fp16 + sniff dtype (block 0) --------
__global__ void prep_kernel(int* __restrict__ cnt, int n,
                            const float4* __restrict__ x4,
                            uint2* __restrict__ xh4, int n4x,
                            const unsigned int* __restrict__ w, int nsamples) {
    int i = blockIdx.x * blockDim.x + threadIdx.x;
    if (i < n) cnt[i] = 0;
    if (i < n4x) {
        float4 v = x4[i];
        uint2 o;
        o.x = h2_to_u32(__floats2half2_rn(v.x, v.y));
        o.y = h2_to_u32(__floats2half2_rn(v.z, v.w));
        xh4[i] = o;
    }
    if (blockIdx.x == 0) {
        int nz = 0;
        for (int k = threadIdx.x; k < nsamples; k += blockDim.x)
            nz |= (w[2 * k + 1] != 0u) ? 1 : 0;
        nz = __syncthreads_or(nz);
        if (threadIdx.x == 0) g_is64 = nz ? 0 : 1;
    }
}

// -------- count in-degree (pair reads; R8-proven shape) --------
__global__ void count_kernel(const void* __restrict__ ei,
                             int* __restrict__ cnt, int E, int N) {
    int is64 = g_is64;
    int stride = gridDim.x * blockDim.x;
    int P = E >> 1;
    if (is64) {
        const longlong2* p = (const longlong2*)((const long long*)ei + E);
        for (int i = blockIdx.x * blockDim.x + threadIdx.x; i < P; i += stride) {
            longlong2 v = p[i];
            int d0 = (int)v.x, d1 = (int)v.y;
            if (d0 >= 0 && d0 < N) atomicAdd(&cnt[d0], 1);
            if (d1 >= 0 && d1 < N) atomicAdd(&cnt[d1], 1);
        }
    } else {
        const int2* p = (const int2*)((const int*)ei + E);
        for (int i = blockIdx.x * blockDim.x + threadIdx.x; i < P; i += stride) {
            int2 v = p[i];
            if (v.x >= 0 && v.x < N) atomicAdd(&cnt[v.x], 1);
            if (v.y >= 0 && v.y < N) atomicAdd(&cnt[v.y], 1);
        }
    }
}

// -------- scan stage 1 --------
__global__ void scan1_kernel(const int* __restrict__ cnt,
                             int* __restrict__ rowptr,
                             int* __restrict__ bsum, int N) {
    __shared__ int sh[1024];
    int gid = blockIdx.x * 1024 + threadIdx.x;
    int v = (gid < N) ? cnt[gid] : 0;
    sh[threadIdx.x] = v;
    __syncthreads();
    for (int off = 1; off < 1024; off <<= 1) {
        int t = (threadIdx.x >= off) ? sh[threadIdx.x - off] : 0;
        __syncthreads();
        sh[threadIdx.x] += t;
        __syncthreads();
    }
    if (gid < N) rowptr[gid] = sh[threadIdx.x] - v;
    if (threadIdx.x == 1023) bsum[blockIdx.x] = sh[1023];
}

// -------- scan stage 2+3: finalize rowptr; cursor = rowptr (write pointer) --------
__global__ void scan23_kernel(int* __restrict__ rowptr,
                              const int* __restrict__ bsum,
                              int* __restrict__ cursor, int N, int E, int nb) {
    __shared__ int sh[NB_MAX];
    if (threadIdx.x < NB_MAX)
        sh[threadIdx.x] = (threadIdx.x < nb) ? bsum[threadIdx.x] : 0;
    __syncthreads();
    for (int off = 1; off < NB_MAX; off <<= 1) {
        int t = (threadIdx.x < NB_MAX && threadIdx.x >= off) ? sh[threadIdx.x - off] : 0;
        __syncthreads();
        if (threadIdx.x < NB_MAX) sh[threadIdx.x] += t;
        __syncthreads();
    }
    int gid = blockIdx.x * blockDim.x + threadIdx.x;
    if (gid < N) {
        int w = gid >> 10;
        int rp = rowptr[gid] + ((w > 0) ? sh[w - 1] : 0);
        rowptr[gid] = rp;
        cursor[gid] = rp;          // absolute write pointer
    }
    if (gid == 0) rowptr[N] = E;
}

// -------- fill CSR: cursor IS the write index (no rowptr read) --------
__global__ void fill_kernel(const void* __restrict__ ei,
                            int* __restrict__ cursor,
                            int* __restrict__ csr_src, int E, int N) {
    int is64 = g_is64;
    int stride = gridDim.x * blockDim.x;
    int P = E >> 1;
    if (is64) {
        const longlong2* ps = (const longlong2*)ei;
        const longlong2* pd = (const longlong2*)((const long long*)ei + E);
        for (int i = blockIdx.x * blockDim.x + threadIdx.x; i < P; i += stride) {
            longlong2 sv = ps[i], dv = pd[i];
            int s0 = (int)sv.x, s1 = (int)sv.y;
            int d0 = (int)dv.x, d1 = (int)dv.y;
            if (d0 >= 0 && d0 < N) { int p = atomicAdd(&cursor[d0], 1); csr_src[p] = s0; }
            if (d1 >= 0 && d1 < N) { int p = atomicAdd(&cursor[d1], 1); csr_src[p] = s1; }
        }
    } else {
        const int2* ps = (const int2*)ei;
        const int2* pd = (const int2*)((const int*)ei + E);
        for (int i = blockIdx.x * blockDim.x + threadIdx.x; i < P; i += stride) {
            int2 sv = ps[i], dv = pd[i];
            if (dv.x >= 0 && dv.x < N) { int p = atomicAdd(&cursor[dv.x], 1); csr_src[p] = sv.x; }
            if (dv.y >= 0 && dv.y < N) { int p = atomicAdd(&cursor[dv.y], 1); csr_src[p] = sv.y; }
        }
    }
}

// -------- gather 1 (fp16 rows, 64B): mean[n] = (1/deg) * sum x_h[s] --------
// Warp per node. 8 groups x 4 lanes; group g loads row (e+g), lane c loads
// 16B (8 halves). Stride 8 -> 8 rows in flight. fp32 accumulation.
__global__ void gather1_kernel(const __half* __restrict__ xh,
                               const int* __restrict__ rowptr,
                               const int* __restrict__ csr_src,
                               float* __restrict__ mean, int N) {
    int lane = threadIdx.x & 31;
    int g = lane >> 2;          // 0..7
    int c = lane & 3;           // 0..3 (halves [c*8, c*8+8))
    int n = blockIdx.x * (blockDim.x >> 5) + (threadIdx.x >> 5);
    if (n >= N) return;

    int s0 = rowptr[n];
    int s1 = rowptr[n + 1];
    int deg = s1 - s0;

    float a[8];
#pragma unroll
    for (int k = 0; k < 8; k++) a[k] = 0.0f;

    for (int e = s0; e < s1; e += 8) {          // warp-uniform bound
        int i = e + g;
        bool v = i < s1;
        int sid = v ? csr_src[i] : 0;
        uint4 raw = ((const uint4*)(xh + (size_t)sid * 32))[c];
        if (v) {
            float2 f0 = __half22float2(u32_to_h2(raw.x));
            float2 f1 = __half22float2(u32_to_h2(raw.y));
            float2 f2 = __half22float2(u32_to_h2(raw.z));
            float2 f3 = __half22float2(u32_to_h2(raw.w));
            a[0] += f0.x; a[1] += f0.y; a[2] += f1.x; a[3] += f1.y;
            a[4] += f2.x; a[5] += f2.y; a[6] += f3.x; a[7] += f3.y;
        }
    }
    // reduce across 8 groups (xor 4, 8, 16); c preserved
#pragma unroll
    for (int s = 4; s <= 16; s <<= 1) {
#pragma unroll
        for (int k = 0; k < 8; k++)
            a[k] += __shfl_xor_sync(0xffffffffu, a[k], s);
    }
    if (g == 0) {
        float inv = 1.0f / (float)max(deg, 1);
        float4 m0 = make_float4(a[0] * inv, a[1] * inv, a[2] * inv, a[3] * inv);
        float4 m1 = make_float4(a[4] * inv, a[5] * inv, a[6] * inv, a[7] * inv);
        float4* mp = (float4*)(mean + (size_t)n * 32 + (size_t)c * 8);
        mp[0] = m0;
        mp[1] = m1;
    }
}

// -------- fused dense: h = relu(mean@W1l + x@W1r + b1); z2h = h@W2l (fp16);
//          r2 = h@W2r + b2 (fp32) --------
__global__ void dense_kernel(const float* __restrict__ x,
                             const float* __restrict__ mean,
                             const float* __restrict__ W1l,
                             const float* __restrict__ W1r,
                             const float* __restrict__ b1,
                             const float* __restrict__ W2l,
                             const float* __restrict__ W2r,
                             const float* __restrict__ b2,
                             __half* __restrict__ z2h,
                             float* __restrict__ r2, int N) {
    int lane = threadIdx.x & 31;
    int warp = (blockIdx.x * blockDim.x + threadIdx.x) >> 5;
    int nwarps = (gridDim.x * blockDim.x) >> 5;

    float wl1[32], wr1[32], w2[32];
#pragma unroll
    for (int k = 0; k < 32; k++) {
        wl1[k] = W1l[k * 32 + lane];
        wr1[k] = W1r[k * 32 + lane];
    }
    int j = lane & 15;
    bool left = lane < 16;
#pragma unroll
    for (int k = 0; k < 32; k++)
        w2[k] = left ? W2l[k * 16 + j] : W2r[k * 16 + j];
    float b1j = b1[lane];
    float b2j = left ? 0.0f : b2[j];

    for (int n = warp; n < N; n += nwarps) {
        float mv = mean[(size_t)n * 32 + lane];
        float xv = x[(size_t)n * 32 + lane];

        float r = b1j;
#pragma unroll
        for (int k = 0; k < 32; k++) {
            float mk = __shfl_sync(0xffffffffu, mv, k);
            float xk = __shfl_sync(0xffffffffu, xv, k);
            r = fmaf(mk, wl1[k], fmaf(xk, wr1[k], r));
        }
        float h = fmaxf(r, 0.0f);

        float acc = b2j;
#pragma unroll
        for (int k = 0; k < 32; k++) {
            float hk = __shfl_sync(0xffffffffu, h, k);
            acc = fmaf(hk, w2[k], acc);
        }
        if (left) z2h[(size_t)n * 16 + j] = __float2half_rn(acc);
        else      r2[(size_t)n * 16 + j] = acc;
    }
}

// -------- gather 2 (fp16 rows, 32B): out[n] = (1/deg)*sum z2h[s] + r2[n] --------
// Warp per node. 16 groups x 2 lanes; stride 16 -> 16 rows in flight.
__global__ void gather2_kernel(const __half* __restrict__ z2h,
                               const float* __restrict__ r2,
                               const int* __restrict__ rowptr,
                               const int* __restrict__ csr_src,
                               float* __restrict__ out, int N) {
    int lane = threadIdx.x & 31;
    int g = lane >> 1;          // 0..15
    int c = lane & 1;           // 0..1 (halves [c*8, c*8+8))
    int n = blockIdx.x * (blockDim.x >> 5) + (threadIdx.x >> 5);
    if (n >= N) return;

    int s0 = rowptr[n];
    int s1 = rowptr[n + 1];
    int deg = s1 - s0;

    float a[8];
#pragma unroll
    for (int k = 0; k < 8; k++) a[k] = 0.0f;

    for (int e = s0; e < s1; e += 16) {         // warp-uniform bound
        int i = e + g;
        bool v = i < s1;
        int sid = v ? csr_src[i] : 0;
        uint4 raw = ((const uint4*)(z2h + (size_t)sid * 16))[c];
        if (v) {
            float2 f0 = __half22float2(u32_to_h2(raw.x));
            float2 f1 = __half22float2(u32_to_h2(raw.y));
            float2 f2 = __half22float2(u32_to_h2(raw.z));
            float2 f3 = __half22float2(u32_to_h2(raw.w));
            a[0] += f0.x; a[1] += f0.y; a[2] += f1.x; a[3] += f1.y;
            a[4] += f2.x; a[5] += f2.y; a[6] += f3.x; a[7] += f3.y;
        }
    }
    // reduce across 16 groups (xor 2, 4, 8, 16); c preserved
#pragma unroll
    for (int s = 2; s <= 16; s <<= 1) {
#pragma unroll
        for (int k = 0; k < 8; k++)
            a[k] += __shfl_xor_sync(0xffffffffu, a[k], s);
    }
    if (g == 0) {
        float inv = 1.0f / (float)max(deg, 1);
        const float4* rp = (const float4*)(r2 + (size_t)n * 16 + (size_t)c * 8);
        float4 rr0 = rp[0];
        float4 rr1 = rp[1];
        float4 o0 = make_float4(a[0] * inv + rr0.x, a[1] * inv + rr0.y,
                                a[2] * inv + rr0.z, a[3] * inv + rr0.w);
        float4 o1 = make_float4(a[4] * inv + rr1.x, a[5] * inv + rr1.y,
                                a[6] * inv + rr1.z, a[7] * inv + rr1.w);
        float4* op = (float4*)(out + (size_t)n * 16 + (size_t)c * 8);
        op[0] = o0;
        op[1] = o1;
    }
}

extern "C" void kernel_launch(void* const* d_in, const int* in_sizes, int n_in,
                              void* d_out, int out_size) {
    const float* x   = (const float*)d_in[0];
    const void*  ei  = d_in[1];
    const float* W1l = (const float*)d_in[2];
    const float* W1r = (const float*)d_in[3];
    const float* b1  = (const float*)d_in[4];
    const float* W2l = (const float*)d_in[5];
    const float* W2r = (const float*)d_in[6];
    const float* b2  = (const float*)d_in[7];
    float* out = (float*)d_out;

    int N = in_sizes[0] / 32;   // 100000
    int E = in_sizes[1] / 2;    // 1600000

    __half *xh, *z2h;
    float *mean, *r2;
    int *rowptr, *cnt, *cursor, *csr_src, *bsum;
    cudaGetSymbolAddress((void**)&xh, g_xh);
    cudaGetSymbolAddress((void**)&mean, g_mean);
    cudaGetSymbolAddress((void**)&z2h, g_z2h);
    cudaGetSymbolAddress((void**)&r2, g_r2);
    cudaGetSymbolAddress((void**)&rowptr, g_rowptr);
    cudaGetSymbolAddress((void**)&cnt, g_cnt);
    cudaGetSymbolAddress((void**)&cursor, g_cursor);
    cudaGetSymbolAddress((void**)&csr_src, g_csr_src);
    cudaGetSymbolAddress((void**)&bsum, g_bsum);

    int nb = (N + 1023) / 1024;           // 98
    int gblocks = (N + 7) / 8;            // 8 warps per 256-thread block
    int n4x = N * 8;                      // x float4 count

    // ---- prep: zero cnt, convert x->fp16, sniff dtype ----
    prep_kernel<<<(n4x + 255) / 256, 256>>>(cnt, N, (const float4*)x,
                                            (uint2*)xh, n4x,
                                            (const unsigned int*)ei, 4096);
    // ---- CSR build ----
    count_kernel<<<2048, 256>>>(ei, cnt, E, N);
    scan1_kernel<<<nb, 1024>>>(cnt, rowptr, bsum, N);
    scan23_kernel<<<(N + 255) / 256, 256>>>(rowptr, bsum, cursor, N, E, nb);
    fill_kernel<<<2048, 256>>>(ei, cursor, csr_src, E, N);

    // ---- layer 1 gather (fp16 payload) ----
    gather1_kernel<<<gblocks, 256>>>(xh, rowptr, csr_src, mean, N);
    // ---- fused dense ----
    dense_kernel<<<2048, 256>>>(x, mean, W1l, W1r, b1, W2l, W2r, b2, z2h, r2, N);
    // ---- layer 2 gather (fp16 payload) + epilogue ----
    gather2_kernel<<<gblocks, 256>>>(z2h, r2, rowptr, csr_src, out, N);
}

// round 15
// speedup vs baseline: 1.1355x; 1.0612x over previous
#include <cuda_runtime.h>
#include <cuda_bf16.h>
#include <cstdint>

// -------- scratch (device globals; no allocation allowed) --------
#define NMAX 100000
#define EMAX 1600000
#define NB_MAX 128            // ceil(NMAX/1024) = 98 <= 128

__device__ __align__(16) float g_mean[(size_t)NMAX * 32]; // mean of neighbor x rows
__device__ __align__(16) float g_z2[(size_t)NMAX * 16];   // h @ W2l
__device__ __align__(16) float g_r2[(size_t)NMAX * 16];   // h @ W2r + b2
__device__ int g_rowptr[NMAX + 1];
__device__ int g_cnt[NMAX];
__device__ int g_cursor[NMAX];
__device__ int g_csr_src[EMAX];
__device__ int g_bsum[NB_MAX];
__device__ int g_is64;

// -------- zero cnt + sniff dtype (block 0) --------
__global__ void zero_sniff_kernel(int* __restrict__ cnt, int n,
                                  const unsigned int* __restrict__ w,
                                  int nsamples) {
    int i = blockIdx.x * blockDim.x + threadIdx.x;
    if (i < n) cnt[i] = 0;
    if (blockIdx.x == 0) {
        int nz = 0;
        for (int k = threadIdx.x; k < nsamples; k += blockDim.x)
            nz |= (w[2 * k + 1] != 0u) ? 1 : 0;
        nz = __syncthreads_or(nz);
        if (threadIdx.x == 0) g_is64 = nz ? 0 : 1;
    }
}

// -------- count in-degree (vectorized pair reads) --------
__global__ void count_kernel(const void* __restrict__ ei,
                             int* __restrict__ cnt, int E, int N) {
    int is64 = g_is64;
    int stride = gridDim.x * blockDim.x;
    int P = E >> 1;   // E even
    if (is64) {
        const longlong2* p = (const longlong2*)((const long long*)ei + E);
        for (int i = blockIdx.x * blockDim.x + threadIdx.x; i < P; i += stride) {
            longlong2 v = p[i];
            int d0 = (int)v.x, d1 = (int)v.y;
            if (d0 >= 0 && d0 < N) atomicAdd(&cnt[d0], 1);
            if (d1 >= 0 && d1 < N) atomicAdd(&cnt[d1], 1);
        }
    } else {
        const int2* p = (const int2*)((const int*)ei + E);
        for (int i = blockIdx.x * blockDim.x + threadIdx.x; i < P; i += stride) {
            int2 v = p[i];
            if (v.x >= 0 && v.x < N) atomicAdd(&cnt[v.x], 1);
            if (v.y >= 0 && v.y < N) atomicAdd(&cnt[v.y], 1);
        }
    }
}

// -------- scan stage 1: per-1024-block exclusive scan + block totals --------
__global__ void scan1_kernel(const int* __restrict__ cnt,
                             int* __restrict__ rowptr,
                             int* __restrict__ bsum, int N) {
    __shared__ int sh[1024];
    int gid = blockIdx.x * 1024 + threadIdx.x;
    int v = (gid < N) ? cnt[gid] : 0;
    sh[threadIdx.x] = v;
    __syncthreads();
    for (int off = 1; off < 1024; off <<= 1) {
        int t = (threadIdx.x >= off) ? sh[threadIdx.x - off] : 0;
        __syncthreads();
        sh[threadIdx.x] += t;
        __syncthreads();
    }
    if (gid < N) rowptr[gid] = sh[threadIdx.x] - v;   // exclusive within block
    if (threadIdx.x == 1023) bsum[blockIdx.x] = sh[1023];
}

// -------- scan stage 2+3: finalize rowptr; cursor = rowptr (write pointer) --------
__global__ void scan23_kernel(int* __restrict__ rowptr,
                              const int* __restrict__ bsum,
                              int* __restrict__ cursor, int N, int E, int nb) {
    __shared__ int sh[NB_MAX];
    if (threadIdx.x < NB_MAX)
        sh[threadIdx.x] = (threadIdx.x < nb) ? bsum[threadIdx.x] : 0;
    __syncthreads();
    for (int off = 1; off < NB_MAX; off <<= 1) {
        int t = (threadIdx.x < NB_MAX && threadIdx.x >= off) ? sh[threadIdx.x - off] : 0;
        __syncthreads();
        if (threadIdx.x < NB_MAX) sh[threadIdx.x] += t;   // inclusive
        __syncthreads();
    }
    int gid = blockIdx.x * blockDim.x + threadIdx.x;
    if (gid < N) {
        int w = gid >> 10;
        int rp = rowptr[gid] + ((w > 0) ? sh[w - 1] : 0);
        rowptr[gid] = rp;
        cursor[gid] = rp;          // absolute write pointer
    }
    if (gid == 0) rowptr[N] = E;
}

// -------- fill CSR: cursor IS the write index (no rowptr read) --------
__global__ void fill_kernel(const void* __restrict__ ei,
                            int* __restrict__ cursor,
                            int* __restrict__ csr_src, int E, int N) {
    int is64 = g_is64;
    int stride = gridDim.x * blockDim.x;
    int P = E >> 1;
    if (is64) {
        const longlong2* ps = (const longlong2*)ei;
        const longlong2* pd = (const longlong2*)((const long long*)ei + E);
        for (int i = blockIdx.x * blockDim.x + threadIdx.x; i < P; i += stride) {
            longlong2 sv = ps[i], dv = pd[i];
            int s0 = (int)sv.x, s1 = (int)sv.y;
            int d0 = (int)dv.x, d1 = (int)dv.y;
            if (d0 >= 0 && d0 < N) { int p = atomicAdd(&cursor[d0], 1); csr_src[p] = s0; }
            if (d1 >= 0 && d1 < N) { int p = atomicAdd(&cursor[d1], 1); csr_src[p] = s1; }
        }
    } else {
        const int2* ps = (const int2*)ei;
        const int2* pd = (const int2*)((const int*)ei + E);
        for (int i = blockIdx.x * blockDim.x + threadIdx.x; i < P; i += stride) {
            int2 sv = ps[i], dv = pd[i];
            if (dv.x >= 0 && dv.x < N) { int p = atomicAdd(&cursor[dv.x], 1); csr_src[p] = sv.x; }
            if (dv.y >= 0 && dv.y < N) { int p = atomicAdd(&cursor[dv.y], 1); csr_src[p] = sv.y; }
        }
    }
}

// -------- gather 1: mean[n] = (1/deg) * sum_{s in N(n)} x[s]   (rows 128B) --------
// Warp per node. 4 groups x 8 lanes; stride 8 -> 8 rows in flight per warp.
__global__ void gather1_kernel(const float* __restrict__ x,
                               const int* __restrict__ rowptr,
                               const int* __restrict__ csr_src,
                               float* __restrict__ mean, int N) {
    int lane = threadIdx.x & 31;
    int g = lane >> 3;          // 0..3
    int c = lane & 7;           // 0..7
    int n = blockIdx.x * (blockDim.x >> 5) + (threadIdx.x >> 5);
    if (n >= N) return;

    int s0 = rowptr[n];
    int s1 = rowptr[n + 1];
    int deg = s1 - s0;

    float4 a0 = make_float4(0.f, 0.f, 0.f, 0.f);
    float4 a1 = make_float4(0.f, 0.f, 0.f, 0.f);
    for (int e = s0; e < s1; e += 8) {         // warp-uniform bound
        int i0 = e + g;
        int i1 = e + 4 + g;
        bool v0 = i0 < s1;
        bool v1 = i1 < s1;
        int sid0 = v0 ? csr_src[i0] : 0;
        int sid1 = v1 ? csr_src[i1] : 0;
        float4 r0 = ((const float4*)(x + (size_t)sid0 * 32))[c];
        float4 r1 = ((const float4*)(x + (size_t)sid1 * 32))[c];
        if (v0) { a0.x += r0.x; a0.y += r0.y; a0.z += r0.z; a0.w += r0.w; }
        if (v1) { a1.x += r1.x; a1.y += r1.y; a1.z += r1.z; a1.w += r1.w; }
    }
    a0.x += a1.x; a0.y += a1.y; a0.z += a1.z; a0.w += a1.w;
    // reduce across 4 groups (xor 8, 16)
#pragma unroll
    for (int s = 8; s <= 16; s <<= 1) {
        a0.x += __shfl_xor_sync(0xffffffffu, a0.x, s);
        a0.y += __shfl_xor_sync(0xffffffffu, a0.y, s);
        a0.z += __shfl_xor_sync(0xffffffffu, a0.z, s);
        a0.w += __shfl_xor_sync(0xffffffffu, a0.w, s);
    }
    if (g == 0) {
        float inv = 1.0f / (float)max(deg, 1);
        float4 m = make_float4(a0.x * inv, a0.y * inv, a0.z * inv, a0.w * inv);
        ((float4*)(mean + (size_t)n * 32))[c] = m;
    }
}

// -------- fused dense: h = relu(mean@W1l + x@W1r + b1); z2 = h@W2l; r2 = h@W2r + b2 --------
__global__ void dense_kernel(const float* __restrict__ x,
                             const float* __restrict__ mean,
                             const float* __restrict__ W1l,
                             const float* __restrict__ W1r,
                             const float* __restrict__ b1,
                             const float* __restrict__ W2l,
                             const float* __restrict__ W2r,
                             const float* __restrict__ b2,
                             float* __restrict__ z2,
                             float* __restrict__ r2, int N) {
    int lane = threadIdx.x & 31;
    int warp = (blockIdx.x * blockDim.x + threadIdx.x) >> 5;
    int nwarps = (gridDim.x * blockDim.x) >> 5;

    float wl1[32], wr1[32], w2[32];
#pragma unroll
    for (int k = 0; k < 32; k++) {
        wl1[k] = W1l[k * 32 + lane];
        wr1[k] = W1r[k * 32 + lane];
    }
    int j = lane & 15;
    bool left = lane < 16;
#pragma unroll
    for (int k = 0; k < 32; k++)
        w2[k] = left ? W2l[k * 16 + j] : W2r[k * 16 + j];
    float b1j = b1[lane];
    float b2j = left ? 0.0f : b2[j];

    for (int n = warp; n < N; n += nwarps) {
        float mv = mean[(size_t)n * 32 + lane];
        float xv = x[(size_t)n * 32 + lane];

        float r = b1j;
#pragma unroll
        for (int k = 0; k < 32; k++) {
            float mk = __shfl_sync(0xffffffffu, mv, k);
            float xk = __shfl_sync(0xffffffffu, xv, k);
            r = fmaf(mk, wl1[k], fmaf(xk, wr1[k], r));
        }
        float h = fmaxf(r, 0.0f);

        float acc = b2j;
#pragma unroll
        for (int k = 0; k < 32; k++) {
            float hk = __shfl_sync(0xffffffffu, h, k);
            acc = fmaf(hk, w2[k], acc);
        }
        if (left) z2[(size_t)n * 16 + j] = acc;
        else      r2[(size_t)n * 16 + j] = acc;
    }
}

// -------- gather 2: out[n] = (1/deg) * sum_{s} z2[s] + r2[n]   (rows 64B) --------
// Warp per node. 8 groups x 4 lanes; stride 16 -> 16 rows in flight per warp.
__global__ void gather2_kernel(const float* __restrict__ z2,
                               const float* __restrict__ r2,
                               const int* __restrict__ rowptr,
                               const int* __restrict__ csr_src,
                               float* __restrict__ out, int N) {
    int lane = threadIdx.x & 31;
    int g = lane >> 2;          // 0..7
    int c = lane & 3;           // 0..3
    int n = blockIdx.x * (blockDim.x >> 5) + (threadIdx.x >> 5);
    if (n >= N) return;

    int s0 = rowptr[n];
    int s1 = rowptr[n + 1];
    int deg = s1 - s0;

    float4 a0 = make_float4(0.f, 0.f, 0.f, 0.f);
    float4 a1 = make_float4(0.f, 0.f, 0.f, 0.f);
    for (int e = s0; e < s1; e += 16) {        // warp-uniform bound
        int i0 = e + g;
        int i1 = e + 8 + g;
        bool v0 = i0 < s1;
        bool v1 = i1 < s1;
        int sid0 = v0 ? csr_src[i0] : 0;
        int sid1 = v1 ? csr_src[i1] : 0;
        float4 r0 = ((const float4*)(z2 + (size_t)sid0 * 16))[c];
        float4 r1 = ((const float4*)(z2 + (size_t)sid1 * 16))[c];
        if (v0) { a0.x += r0.x; a0.y += r0.y; a0.z += r0.z; a0.w += r0.w; }
        if (v1) { a1.x += r1.x; a1.y += r1.y; a1.z += r1.z; a1.w += r1.w; }
    }
    a0.x += a1.x; a0.y += a1.y; a0.z += a1.z; a0.w += a1.w;
#pragma unroll
    for (int s = 4; s <= 16; s <<= 1) {
        a0.x += __shfl_xor_sync(0xffffffffu, a0.x, s);
        a0.y += __shfl_xor_sync(0xffffffffu, a0.y, s);
        a0.z += __shfl_xor_sync(0xffffffffu, a0.z, s);
        a0.w += __shfl_xor_sync(0xffffffffu, a0.w, s);
    }
    if (g == 0) {
        float inv = 1.0f / (float)max(deg, 1);
        float4 rr = ((const float4*)(r2 + (size_t)n * 16))[c];
        float4 o = make_float4(a0.x * inv + rr.x, a0.y * inv + rr.y,
                               a0.z * inv + rr.z, a0.w * inv + rr.w);
        ((float4*)(out + (size_t)n * 16))[c] = o;
    }
}

extern "C" void kernel_launch(void* const* d_in, const int* in_sizes, int n_in,
                              void* d_out, int out_size) {
    const float* x   = (const float*)d_in[0];
    const void*  ei  = d_in[1];
    const float* W1l = (const float*)d_in[2];
    const float* W1r = (const float*)d_in[3];
    const float* b1  = (const float*)d_in[4];
    const float* W2l = (const float*)d_in[5];
    const float* W2r = (const float*)d_in[6];
    const float* b2  = (const float*)d_in[7];
    float* out = (float*)d_out;

    int N = in_sizes[0] / 32;   // 100000
    int E = in_sizes[1] / 2;    // 1600000

    float *mean, *z2, *r2;
    int *rowptr, *cnt, *cursor, *csr_src, *bsum;
    cudaGetSymbolAddress((void**)&mean, g_mean);
    cudaGetSymbolAddress((void**)&z2, g_z2);
    cudaGetSymbolAddress((void**)&r2, g_r2);
    cudaGetSymbolAddress((void**)&rowptr, g_rowptr);
    cudaGetSymbolAddress((void**)&cnt, g_cnt);
    cudaGetSymbolAddress((void**)&cursor, g_cursor);
    cudaGetSymbolAddress((void**)&csr_src, g_csr_src);
    cudaGetSymbolAddress((void**)&bsum, g_bsum);

    int nb = (N + 1023) / 1024;           // 98
    int gblocks = (N + 7) / 8;            // 8 warps per 256-thread block

    // ---- CSR build ----
    zero_sniff_kernel<<<(N + 255) / 256, 256>>>(cnt, N, (const unsigned int*)ei, 4096);
    count_kernel<<<2048, 256>>>(ei, cnt, E, N);
    scan1_kernel<<<nb, 1024>>>(cnt, rowptr, bsum, N);
    scan23_kernel<<<(N + 255) / 256, 256>>>(rowptr, bsum, cursor, N, E, nb);
    fill_kernel<<<2048, 256>>>(ei, cursor, csr_src, E, N);

    // ---- layer 1 gather ----
    gather1_kernel<<<gblocks, 256>>>(x, rowptr, csr_src, mean, N);
    // ---- fused dense ----
    dense_kernel<<<2048, 256>>>(x, mean, W1l, W1r, b1, W2l, W2r, b2, z2, r2, N);
    // ---- layer 2 gather + epilogue ----
    gather2_kernel<<<gblocks, 256>>>(z2, r2, rowptr, csr_src, out, N);
}

// round 16
// speedup vs baseline: 1.1728x; 1.0328x over previous
#include <cuda_runtime.h>
#include <cuda_bf16.h>
#include <cstdint>

// -------- scratch (device globals; no allocation allowed) --------
#define NMAX 100000
#define EMAX 1600000
#define NB_MAX 128            // ceil(NMAX/1024) = 98 <= 128

__device__ __align__(16) float g_mean[(size_t)NMAX * 32]; // mean of neighbor x rows
__device__ __align__(16) float g_z2[(size_t)NMAX * 16];   // h @ W2l
__device__ __align__(16) float g_r2[(size_t)NMAX * 16];   // h @ W2r + b2
__device__ int g_rowptr[NMAX + 1];
__device__ int g_cnt[NMAX];      // zero-initialized at load; re-zeroed by scan23 each run
__device__ int g_cursor[NMAX];
__device__ int g_csr_src[EMAX];
__device__ int g_bsum[NB_MAX];

// Per-warp dtype sniff: int64 iff the first 32 odd 32-bit words are all zero.
// (int32 edge ids are random in [0,100000); P[32 consecutive are 0] ~ 0.)
__device__ __forceinline__ int sniff_is64(const void* ei) {
    unsigned w = ((const unsigned*)ei)[2 * (threadIdx.x & 31) + 1];
    return __ballot_sync(0xffffffffu, w != 0u) == 0u;
}

// -------- count in-degree (vectorized pair reads; inline sniff) --------
__global__ void count_kernel(const void* __restrict__ ei,
                             int* __restrict__ cnt, int E, int N) {
    int is64 = sniff_is64(ei);
    int stride = gridDim.x * blockDim.x;
    int P = E >> 1;   // E even
    if (is64) {
        const longlong2* p = (const longlong2*)((const long long*)ei + E);
        for (int i = blockIdx.x * blockDim.x + threadIdx.x; i < P; i += stride) {
            longlong2 v = p[i];
            int d0 = (int)v.x, d1 = (int)v.y;
            if (d0 >= 0 && d0 < N) atomicAdd(&cnt[d0], 1);
            if (d1 >= 0 && d1 < N) atomicAdd(&cnt[d1], 1);
        }
    } else {
        const int2* p = (const int2*)((const int*)ei + E);
        for (int i = blockIdx.x * blockDim.x + threadIdx.x; i < P; i += stride) {
            int2 v = p[i];
            if (v.x >= 0 && v.x < N) atomicAdd(&cnt[v.x], 1);
            if (v.y >= 0 && v.y < N) atomicAdd(&cnt[v.y], 1);
        }
    }
}

// -------- scan stage 1: shfl warp scans (2 syncs) --------
__global__ void scan1_kernel(const int* __restrict__ cnt,
                             int* __restrict__ rowptr,
                             int* __restrict__ bsum, int N) {
    __shared__ int wsum[32];
    int lane = threadIdx.x & 31;
    int wid = threadIdx.x >> 5;
    int gid = blockIdx.x * 1024 + threadIdx.x;
    int v = (gid < N) ? cnt[gid] : 0;

    // warp-inclusive scan
    int inc = v;
#pragma unroll
    for (int off = 1; off < 32; off <<= 1) {
        int t = __shfl_up_sync(0xffffffffu, inc, off);
        if (lane >= off) inc += t;
    }
    if (lane == 31) wsum[wid] = inc;
    __syncthreads();
    if (wid == 0) {
        int w = wsum[lane];
        int wi = w;
#pragma unroll
        for (int off = 1; off < 32; off <<= 1) {
            int t = __shfl_up_sync(0xffffffffu, wi, off);
            if (lane >= off) wi += t;
        }
        wsum[lane] = wi;   // inclusive warp totals
    }
    __syncthreads();
    int base = (wid > 0) ? wsum[wid - 1] : 0;
    if (gid < N) rowptr[gid] = base + inc - v;   // exclusive within block
    if (threadIdx.x == 1023) bsum[blockIdx.x] = wsum[31];
}

// -------- scan stage 2+3: single-warp shfl scan of bsum; finalize rowptr;
//          cursor = rowptr (write pointer); re-zero cnt for next run --------
__global__ void scan23_kernel(int* __restrict__ rowptr,
                              const int* __restrict__ bsum,
                              int* __restrict__ cursor,
                              int* __restrict__ cnt, int N, int E, int nb) {
    __shared__ int sb[NB_MAX];   // inclusive prefix of bsum
    if (threadIdx.x < 32) {
        int lane = threadIdx.x;
        int a0 = (lane * 4 + 0 < nb) ? bsum[lane * 4 + 0] : 0;
        int a1 = (lane * 4 + 1 < nb) ? bsum[lane * 4 + 1] : 0;
        int a2 = (lane * 4 + 2 < nb) ? bsum[lane * 4 + 2] : 0;
        int a3 = (lane * 4 + 3 < nb) ? bsum[lane * 4 + 3] : 0;
        int s0 = a0, s1 = s0 + a1, s2 = s1 + a2, s3 = s2 + a3;
        int inc = s3;
#pragma unroll
        for (int off = 1; off < 32; off <<= 1) {
            int t = __shfl_up_sync(0xffffffffu, inc, off);
            if (lane >= off) inc += t;
        }
        int base = inc - s3;
        sb[lane * 4 + 0] = base + s0;
        sb[lane * 4 + 1] = base + s1;
        sb[lane * 4 + 2] = base + s2;
        sb[lane * 4 + 3] = base + s3;
    }
    __syncthreads();
    int gid = blockIdx.x * blockDim.x + threadIdx.x;
    if (gid < N) {
        int w = gid >> 10;
        int rp = rowptr[gid] + ((w > 0) ? sb[w - 1] : 0);
        rowptr[gid] = rp;
        cursor[gid] = rp;          // absolute write pointer
        cnt[gid] = 0;              // reset for next graph replay
    }
    if (gid == 0) rowptr[N] = E;
}

// -------- fill CSR: cursor IS the write index (inline sniff) --------
__global__ void fill_kernel(const void* __restrict__ ei,
                            int* __restrict__ cursor,
                            int* __restrict__ csr_src, int E, int N) {
    int is64 = sniff_is64(ei);
    int stride = gridDim.x * blockDim.x;
    int P = E >> 1;
    if (is64) {
        const longlong2* ps = (const longlong2*)ei;
        const longlong2* pd = (const longlong2*)((const long long*)ei + E);
        for (int i = blockIdx.x * blockDim.x + threadIdx.x; i < P; i += stride) {
            longlong2 sv = ps[i], dv = pd[i];
            int s0 = (int)sv.x, s1 = (int)sv.y;
            int d0 = (int)dv.x, d1 = (int)dv.y;
            if (d0 >= 0 && d0 < N) { int p = atomicAdd(&cursor[d0], 1); csr_src[p] = s0; }
            if (d1 >= 0 && d1 < N) { int p = atomicAdd(&cursor[d1], 1); csr_src[p] = s1; }
        }
    } else {
        const int2* ps = (const int2*)ei;
        const int2* pd = (const int2*)((const int*)ei + E);
        for (int i = blockIdx.x * blockDim.x + threadIdx.x; i < P; i += stride) {
            int2 sv = ps[i], dv = pd[i];
            if (dv.x >= 0 && dv.x < N) { int p = atomicAdd(&cursor[dv.x], 1); csr_src[p] = sv.x; }
            if (dv.y >= 0 && dv.y < N) { int p = atomicAdd(&cursor[dv.y], 1); csr_src[p] = sv.y; }
        }
    }
}

// -------- gather 1: mean[n] = (1/deg) * sum_{s in N(n)} x[s]   (rows 128B) --------
// Warp per node. 4 groups x 8 lanes; stride 8 -> 8 rows in flight per warp.
__global__ void gather1_kernel(const float* __restrict__ x,
                               const int* __restrict__ rowptr,
                               const int* __restrict__ csr_src,
                               float* __restrict__ mean, int N) {
    int lane = threadIdx.x & 31;
    int g = lane >> 3;          // 0..3
    int c = lane & 7;           // 0..7
    int n = blockIdx.x * (blockDim.x >> 5) + (threadIdx.x >> 5);
    if (n >= N) return;

    int s0 = rowptr[n];
    int s1 = rowptr[n + 1];
    int deg = s1 - s0;

    float4 a0 = make_float4(0.f, 0.f, 0.f, 0.f);
    float4 a1 = make_float4(0.f, 0.f, 0.f, 0.f);
    for (int e = s0; e < s1; e += 8) {         // warp-uniform bound
        int i0 = e + g;
        int i1 = e + 4 + g;
        bool v0 = i0 < s1;
        bool v1 = i1 < s1;
        int sid0 = v0 ? csr_src[i0] : 0;
        int sid1 = v1 ? csr_src[i1] : 0;
        float4 r0 = ((const float4*)(x + (size_t)sid0 * 32))[c];
        float4 r1 = ((const float4*)(x + (size_t)sid1 * 32))[c];
        if (v0) { a0.x += r0.x; a0.y += r0.y; a0.z += r0.z; a0.w += r0.w; }
        if (v1) { a1.x += r1.x; a1.y += r1.y; a1.z += r1.z; a1.w += r1.w; }
    }
    a0.x += a1.x; a0.y += a1.y; a0.z += a1.z; a0.w += a1.w;
    // reduce across 4 groups (xor 8, 16)
#pragma unroll
    for (int s = 8; s <= 16; s <<= 1) {
        a0.x += __shfl_xor_sync(0xffffffffu, a0.x, s);
        a0.y += __shfl_xor_sync(0xffffffffu, a0.y, s);
        a0.z += __shfl_xor_sync(0xffffffffu, a0.z, s);
        a0.w += __shfl_xor_sync(0xffffffffu, a0.w, s);
    }
    if (g == 0) {
        float inv = 1.0f / (float)max(deg, 1);
        float4 m = make_float4(a0.x * inv, a0.y * inv, a0.z * inv, a0.w * inv);
        ((float4*)(mean + (size_t)n * 32))[c] = m;
    }
}

// -------- fused dense: h = relu(mean@W1l + x@W1r + b1); z2 = h@W2l; r2 = h@W2r + b2 --------
__global__ void dense_kernel(const float* __restrict__ x,
                             const float* __restrict__ mean,
                             const float* __restrict__ W1l,
                             const float* __restrict__ W1r,
                             const float* __restrict__ b1,
                             const float* __restrict__ W2l,
                             const float* __restrict__ W2r,
                             const float* __restrict__ b2,
                             float* __restrict__ z2,
                             float* __restrict__ r2, int N) {
    int lane = threadIdx.x & 31;
    int warp = (blockIdx.x * blockDim.x + threadIdx.x) >> 5;
    int nwarps = (gridDim.x * blockDim.x) >> 5;

    float wl1[32], wr1[32], w2[32];
#pragma unroll
    for (int k = 0; k < 32; k++) {
        wl1[k] = W1l[k * 32 + lane];
        wr1[k] = W1r[k * 32 + lane];
    }
    int j = lane & 15;
    bool left = lane < 16;
#pragma unroll
    for (int k = 0; k < 32; k++)
        w2[k] = left ? W2l[k * 16 + j] : W2r[k * 16 + j];
    float b1j = b1[lane];
    float b2j = left ? 0.0f : b2[j];

    for (int n = warp; n < N; n += nwarps) {
        float mv = mean[(size_t)n * 32 + lane];
        float xv = x[(size_t)n * 32 + lane];

        float r = b1j;
#pragma unroll
        for (int k = 0; k < 32; k++) {
            float mk = __shfl_sync(0xffffffffu, mv, k);
            float xk = __shfl_sync(0xffffffffu, xv, k);
            r = fmaf(mk, wl1[k], fmaf(xk, wr1[k], r));
        }
        float h = fmaxf(r, 0.0f);

        float acc = b2j;
#pragma unroll
        for (int k = 0; k < 32; k++) {
            float hk = __shfl_sync(0xffffffffu, h, k);
            acc = fmaf(hk, w2[k], acc);
        }
        if (left) z2[(size_t)n * 16 + j] = acc;
        else      r2[(size_t)n * 16 + j] = acc;
    }
}

// -------- gather 2: out[n] = (1/deg) * sum_{s} z2[s] + r2[n]   (rows 64B) --------
// Warp per node. 8 groups x 4 lanes; stride 16 -> 16 rows in flight per warp.
__global__ void gather2_kernel(const float* __restrict__ z2,
                               const float* __restrict__ r2,
                               const int* __restrict__ rowptr,
                               const int* __restrict__ csr_src,
                               float* __restrict__ out, int N) {
    int lane = threadIdx.x & 31;
    int g = lane >> 2;          // 0..7
    int c = lane & 3;           // 0..3
    int n = blockIdx.x * (blockDim.x >> 5) + (threadIdx.x >> 5);
    if (n >= N) return;

    int s0 = rowptr[n];
    int s1 = rowptr[n + 1];
    int deg = s1 - s0;

    float4 a0 = make_float4(0.f, 0.f, 0.f, 0.f);
    float4 a1 = make_float4(0.f, 0.f, 0.f, 0.f);
    for (int e = s0; e < s1; e += 16) {        // warp-uniform bound
        int i0 = e + g;
        int i1 = e + 8 + g;
        bool v0 = i0 < s1;
        bool v1 = i1 < s1;
        int sid0 = v0 ? csr_src[i0] : 0;
        int sid1 = v1 ? csr_src[i1] : 0;
        float4 r0 = ((const float4*)(z2 + (size_t)sid0 * 16))[c];
        float4 r1 = ((const float4*)(z2 + (size_t)sid1 * 16))[c];
        if (v0) { a0.x += r0.x; a0.y += r0.y; a0.z += r0.z; a0.w += r0.w; }
        if (v1) { a1.x += r1.x; a1.y += r1.y; a1.z += r1.z; a1.w += r1.w; }
    }
    a0.x += a1.x; a0.y += a1.y; a0.z += a1.z; a0.w += a1.w;
#pragma unroll
    for (int s = 4; s <= 16; s <<= 1) {
        a0.x += __shfl_xor_sync(0xffffffffu, a0.x, s);
        a0.y += __shfl_xor_sync(0xffffffffu, a0.y, s);
        a0.z += __shfl_xor_sync(0xffffffffu, a0.z, s);
        a0.w += __shfl_xor_sync(0xffffffffu, a0.w, s);
    }
    if (g == 0) {
        float inv = 1.0f / (float)max(deg, 1);
        float4 rr = ((const float4*)(r2 + (size_t)n * 16))[c];
        float4 o = make_float4(a0.x * inv + rr.x, a0.y * inv + rr.y,
                               a0.z * inv + rr.z, a0.w * inv + rr.w);
        ((float4*)(out + (size_t)n * 16))[c] = o;
    }
}

extern "C" void kernel_launch(void* const* d_in, const int* in_sizes, int n_in,
                              void* d_out, int out_size) {
    const float* x   = (const float*)d_in[0];
    const void*  ei  = d_in[1];
    const float* W1l = (const float*)d_in[2];
    const float* W1r = (const float*)d_in[3];
    const float* b1  = (const float*)d_in[4];
    const float* W2l = (const float*)d_in[5];
    const float* W2r = (const float*)d_in[6];
    const float* b2  = (const float*)d_in[7];
    float* out = (float*)d_out;

    int N = in_sizes[0] / 32;   // 100000
    int E = in_sizes[1] / 2;    // 1600000

    float *mean, *z2, *r2;
    int *rowptr, *cnt, *cursor, *csr_src, *bsum;
    cudaGetSymbolAddress((void**)&mean, g_mean);
    cudaGetSymbolAddress((void**)&z2, g_z2);
    cudaGetSymbolAddress((void**)&r2, g_r2);
    cudaGetSymbolAddress((void**)&rowptr, g_rowptr);
    cudaGetSymbolAddress((void**)&cnt, g_cnt);
    cudaGetSymbolAddress((void**)&cursor, g_cursor);
    cudaGetSymbolAddress((void**)&csr_src, g_csr_src);
    cudaGetSymbolAddress((void**)&bsum, g_bsum);

    int nb = (N + 1023) / 1024;           // 98
    int gblocks = (N + 7) / 8;            // 8 warps per 256-thread block

    // ---- CSR build (4 launches; cnt starts zero: load-time init + scan23 reset) ----
    count_kernel<<<2048, 256>>>(ei, cnt, E, N);
    scan1_kernel<<<nb, 1024>>>(cnt, rowptr, bsum, N);
    scan23_kernel<<<(N + 255) / 256, 256>>>(rowptr, bsum, cursor, cnt, N, E, nb);
    fill_kernel<<<2048, 256>>>(ei, cursor, csr_src, E, N);

    // ---- layer 1 gather ----
    gather1_kernel<<<gblocks, 256>>>(x, rowptr, csr_src, mean, N);
    // ---- fused dense ----
    dense_kernel<<<2048, 256>>>(x, mean, W1l, W1r, b1, W2l, W2r, b2, z2, r2, N);
    // ---- layer 2 gather + epilogue ----
    gather2_kernel<<<gblocks, 256>>>(z2, r2, rowptr, csr_src, out, N);
}